// round 2
// baseline (speedup 1.0000x reference)
#include <cuda_runtime.h>
#include <math.h>

// MultiStepUnitaryGCN collapses algebraically: star-graph evolution weights are
// Re(exp(-itA)[0,:]) = [cos(t*sqrt(d)), 0, ..., 0]  (off-center entries purely
// imaginary since exp(-itA) = cos(tA) - i*sin(tA), cos(tA)[0,j]=0 for leaves),
// smax == 1 (G unitary). So neighbors contribute nothing:
//   h   = relu(cos(sqrt(d)) * (x @ W1^T) + b1)
//   o   = cos(0.5*sqrt(d)) * (h @ W2^T) + b2
//   out = log_softmax(o, axis=1)
// Fully fused per-node MLP, one kernel. nbr_mask arrives as int32 [N,16].

#define N_NODES 50000
#define KNBR    16
#define CIN     128
#define CHID    128
#define COUT    64
#define TM      64          // rows (nodes) per block
#define NTHREADS 256
#define W1_STRIDE 132       // padded (mult of 4) to reduce transpose-store conflicts
#define W2_STRIDE 68

// shared layout (floats):
//   sW1t : CIN * W1_STRIDE        = 16896   (W1 transposed: [k][c])
//   sW2t : CHID * W2_STRIDE       =  8704   (W2 transposed: [k][c])
//   sX   : TM * CIN               =  8192   (x tile; reused for h)
//   sC1, sC2 : TM each            =   128
//   sB1  : CHID                   =   128
//   sB2  : COUT                   =    64
#define SMEM_FLOATS (CIN*W1_STRIDE + CHID*W2_STRIDE + TM*CIN + 2*TM + CHID + COUT)
#define SMEM_BYTES  (SMEM_FLOATS * 4)

__global__ void __launch_bounds__(NTHREADS, 1)
fused_gcn_kernel(const float* __restrict__ x,
                 const int* __restrict__ mask,   // bool [N,K] widened to int32
                 const float* __restrict__ W1,
                 const float* __restrict__ b1,
                 const float* __restrict__ W2,
                 const float* __restrict__ b2,
                 float* __restrict__ out)
{
    extern __shared__ float smem[];
    float* sW1t = smem;
    float* sW2t = sW1t + CIN * W1_STRIDE;
    float* sX   = sW2t + CHID * W2_STRIDE;
    float* sC1  = sX + TM * CIN;
    float* sC2  = sC1 + TM;
    float* sB1  = sC2 + TM;
    float* sB2  = sB1 + CHID;
    float* sO   = sW1t;    // [TM][COUT] reuse after GEMM1 done with sW1t

    const int tid  = threadIdx.x;
    const int row0 = blockIdx.x * TM;

    // ---- stage W1 transposed: sW1t[k*W1_STRIDE + c] = W1[c*CIN + k]
    for (int idx = tid; idx < CHID * CIN; idx += NTHREADS) {
        int c = idx >> 7;          // CIN == 128
        int k = idx & 127;
        sW1t[k * W1_STRIDE + c] = W1[idx];
    }
    // ---- stage W2 transposed: sW2t[k*W2_STRIDE + c] = W2[c*CHID + k]
    for (int idx = tid; idx < COUT * CHID; idx += NTHREADS) {
        int c = idx >> 7;          // CHID == 128
        int k = idx & 127;
        sW2t[k * W2_STRIDE + c] = W2[idx];
    }
    if (tid < CHID) sB1[tid] = b1[tid];
    if (tid < COUT) sB2[tid] = b2[tid];

    // ---- stage x tile (float4, zero-pad OOB rows)
    {
        const float4* xv  = (const float4*)x;
        float4*       sXv = (float4*)sX;
        const int base = row0 * (CIN / 4);
        for (int idx = tid; idx < TM * (CIN / 4); idx += NTHREADS) {
            int r = idx / (CIN / 4);
            float4 v = make_float4(0.f, 0.f, 0.f, 0.f);
            if (row0 + r < N_NODES) v = xv[base + idx];
            sXv[idx] = v;
        }
    }

    // ---- degree -> cos factors (mask is int32 0/1, 16 per node)
    if (tid < TM) {
        int r = row0 + tid;
        float c1 = 0.f, c2 = 0.f;
        if (r < N_NODES) {
            const int4* mp = (const int4*)(mask + (size_t)r * KNBR);
            int4 m0 = mp[0], m1 = mp[1], m2 = mp[2], m3 = mp[3];
            int d = m0.x + m0.y + m0.z + m0.w
                  + m1.x + m1.y + m1.z + m1.w
                  + m2.x + m2.y + m2.z + m2.w
                  + m3.x + m3.y + m3.z + m3.w;
            float sd = sqrtf((float)d);
            c1 = cosf(sd);          // T1 = 1.0
            c2 = cosf(0.5f * sd);   // T2 = 0.5
        }
        sC1[tid] = c1;
        sC2[tid] = c2;
    }
    __syncthreads();

    const int warp = tid >> 5;     // 0..7 -> row group (8 rows each)
    const int lane = tid & 31;     // col group
    const float* aBase = sX + (warp * 8) * CIN;

    // ---- GEMM1: h[64][128] = x @ W1^T ; thread tile 8 rows x 4 cols
    float acc[8][4];
#pragma unroll
    for (int i = 0; i < 8; ++i)
#pragma unroll
        for (int j = 0; j < 4; ++j) acc[i][j] = 0.f;

#pragma unroll 4
    for (int k = 0; k < CIN; ++k) {
        float4 b = *(const float4*)(sW1t + k * W1_STRIDE + lane * 4);
#pragma unroll
        for (int i = 0; i < 8; ++i) {
            float a = aBase[i * CIN + k];
            acc[i][0] = fmaf(a, b.x, acc[i][0]);
            acc[i][1] = fmaf(a, b.y, acc[i][1]);
            acc[i][2] = fmaf(a, b.z, acc[i][2]);
            acc[i][3] = fmaf(a, b.w, acc[i][3]);
        }
    }
    __syncthreads();   // everyone done reading sX and sW1t

    // epilogue: h = relu(c1*acc + b1), store into sX (reused)
    {
        float4 bb = *(const float4*)(sB1 + lane * 4);
#pragma unroll
        for (int i = 0; i < 8; ++i) {
            int r = warp * 8 + i;
            float c1 = sC1[r];
            float4 h;
            h.x = fmaxf(fmaf(c1, acc[i][0], bb.x), 0.f);
            h.y = fmaxf(fmaf(c1, acc[i][1], bb.y), 0.f);
            h.z = fmaxf(fmaf(c1, acc[i][2], bb.z), 0.f);
            h.w = fmaxf(fmaf(c1, acc[i][3], bb.w), 0.f);
            *(float4*)(sX + r * CIN + lane * 4) = h;
        }
    }
    __syncthreads();

    // ---- GEMM2: o[64][64] = h @ W2^T ; thread tile 8 rows x 2 cols
    float acc2[8][2];
#pragma unroll
    for (int i = 0; i < 8; ++i) { acc2[i][0] = 0.f; acc2[i][1] = 0.f; }

#pragma unroll 4
    for (int k = 0; k < CHID; ++k) {
        float2 b = *(const float2*)(sW2t + k * W2_STRIDE + lane * 2);
#pragma unroll
        for (int i = 0; i < 8; ++i) {
            float a = aBase[i * CIN + k];
            acc2[i][0] = fmaf(a, b.x, acc2[i][0]);
            acc2[i][1] = fmaf(a, b.y, acc2[i][1]);
        }
    }
    // write o = c2*acc2 + b2 into sO (aliases sW1t; sW1t reads ended 2 syncs ago)
#pragma unroll
    for (int i = 0; i < 8; ++i) {
        int r = warp * 8 + i;
        float c2v = sC2[r];
        sO[r * COUT + lane * 2 + 0] = fmaf(c2v, acc2[i][0], sB2[lane * 2 + 0]);
        sO[r * COUT + lane * 2 + 1] = fmaf(c2v, acc2[i][1], sB2[lane * 2 + 1]);
    }
    __syncthreads();

    // ---- log_softmax per row; each warp handles 8 rows, 2 cols per lane
#pragma unroll
    for (int j = 0; j < 8; ++j) {
        int r = warp * 8 + j;
        int grow = row0 + r;
        if (grow >= N_NODES) continue;     // uniform across warp
        float v0 = sO[r * COUT + lane];
        float v1 = sO[r * COUT + lane + 32];
        float m = fmaxf(v0, v1);
#pragma unroll
        for (int off = 16; off; off >>= 1)
            m = fmaxf(m, __shfl_xor_sync(0xffffffffu, m, off));
        float s = expf(v0 - m) + expf(v1 - m);
#pragma unroll
        for (int off = 16; off; off >>= 1)
            s += __shfl_xor_sync(0xffffffffu, s, off);
        float lse = m + logf(s);
        out[(size_t)grow * COUT + lane]      = v0 - lse;
        out[(size_t)grow * COUT + lane + 32] = v1 - lse;
    }
}

extern "C" void kernel_launch(void* const* d_in, const int* in_sizes, int n_in,
                              void* d_out, int out_size)
{
    // metadata order: x, neighbors, nbr_mask, W1, b1, W2, b2
    const float* x    = (const float*)d_in[0];
    // d_in[1] = neighbors (unused: star-evolution off-center weights are exactly 0)
    const int*   mask = (const int*)d_in[2];
    const float* W1   = (const float*)d_in[3];
    const float* b1   = (const float*)d_in[4];
    const float* W2   = (const float*)d_in[5];
    const float* b2   = (const float*)d_in[6];
    float*       out  = (float*)d_out;

    cudaFuncSetAttribute(fused_gcn_kernel,
                         cudaFuncAttributeMaxDynamicSharedMemorySize, SMEM_BYTES);

    const int grid = (N_NODES + TM - 1) / TM;   // 782
    fused_gcn_kernel<<<grid, NTHREADS, SMEM_BYTES>>>(x, mask, W1, b1, W2, b2, out);
}

// round 3
// speedup vs baseline: 1.4073x; 1.4073x over previous
#include <cuda_runtime.h>
#include <math.h>

// MultiStepUnitaryGCN collapses algebraically: star-graph evolution weights are
// Re(exp(-itA)[0,:]) = [cos(t*sqrt(d)), 0, ..., 0]  => per-node MLP:
//   h   = relu(cos(sqrt(d)) * (x @ W1^T) + b1)
//   o   = cos(0.5*sqrt(d)) * (h @ W2^T) + b2
//   out = log_softmax(o, axis=1)
// nbr_mask arrives as int32 [N,16]; neighbors unused.
//
// R2 -> R3: smem 136.6KB -> 101.6KB (W2t/sO overlay into W1t region) for
// 2 CTAs/SM, and k-quad float4 A-operand loads (12 LDS.128 per 128 FFMA).

#define N_NODES 50000
#define KNBR    16
#define CIN     128
#define CHID    128
#define COUT    64
#define TM      64
#define NTHREADS 256
#define W1S 132            // W1t row stride (floats), mult of 4, conflict-free loads
#define W2S 70             // W2t row stride (floats), even for float2 loads

// shared layout (floats):
//   sW1t : CIN * W1S = 16896       phase A: W1 transposed [k][c]
//          phase B alias: sW2t = [0, 128*70=8960), sO = [8960, 8960+4096)
//   sX   : TM * CIN  = 8192        x tile; reused for h
//   sC1,sC2 : TM each;  sB1 : CHID;  sB2 : COUT
#define SMEM_FLOATS (CIN*W1S + TM*CIN + 2*TM + CHID + COUT)
#define SMEM_BYTES  (SMEM_FLOATS * 4)

__global__ void __launch_bounds__(NTHREADS, 2)
fused_gcn_kernel(const float* __restrict__ x,
                 const int* __restrict__ mask,
                 const float* __restrict__ W1,
                 const float* __restrict__ b1,
                 const float* __restrict__ W2,
                 const float* __restrict__ b2,
                 float* __restrict__ out)
{
    extern __shared__ float smem[];
    float* sW1t = smem;                       // 16896 floats
    float* sW2t = smem;                       // alias (phase B), 8960 floats
    float* sO   = smem + CHID * W2S;          // alias (phase B), 4096 floats
    float* sX   = smem + CIN * W1S;           // 8192 floats
    float* sC1  = sX + TM * CIN;
    float* sC2  = sC1 + TM;
    float* sB1  = sC2 + TM;
    float* sB2  = sB1 + CHID;

    const int tid  = threadIdx.x;
    const int row0 = blockIdx.x * TM;

    // ---- stage W1 transposed: sW1t[k*W1S + c] = W1[c*CIN + k]
    for (int idx = tid; idx < CHID * CIN; idx += NTHREADS) {
        int c = idx >> 7;
        int k = idx & 127;
        sW1t[k * W1S + c] = W1[idx];
    }
    if (tid < CHID) sB1[tid] = b1[tid];
    if (tid < COUT) sB2[tid] = b2[tid];

    // ---- stage x tile (float4, zero-pad OOB rows)
    {
        const float4* xv  = (const float4*)x;
        float4*       sXv = (float4*)sX;
        const int base = row0 * (CIN / 4);
        for (int idx = tid; idx < TM * (CIN / 4); idx += NTHREADS) {
            int r = idx / (CIN / 4);
            float4 v = make_float4(0.f, 0.f, 0.f, 0.f);
            if (row0 + r < N_NODES) v = xv[base + idx];
            sXv[idx] = v;
        }
    }

    // ---- degree -> cos factors (mask int32 0/1)
    if (tid < TM) {
        int r = row0 + tid;
        float c1 = 0.f, c2 = 0.f;
        if (r < N_NODES) {
            const int4* mp = (const int4*)(mask + (size_t)r * KNBR);
            int4 m0 = mp[0], m1 = mp[1], m2 = mp[2], m3 = mp[3];
            int d = m0.x + m0.y + m0.z + m0.w + m1.x + m1.y + m1.z + m1.w
                  + m2.x + m2.y + m2.z + m2.w + m3.x + m3.y + m3.z + m3.w;
            float sd = sqrtf((float)d);
            c1 = cosf(sd);
            c2 = cosf(0.5f * sd);
        }
        sC1[tid] = c1;
        sC2[tid] = c2;
    }
    __syncthreads();

    const int warp = tid >> 5;
    const int lane = tid & 31;
    const float* aBase = sX + (warp * 8) * CIN;

    // ---- GEMM1: h[64][128] = x @ W1^T ; thread tile 8 rows x 4 cols
    float4 acc[8];
#pragma unroll
    for (int i = 0; i < 8; ++i) acc[i] = make_float4(0.f, 0.f, 0.f, 0.f);

#pragma unroll 2
    for (int kq = 0; kq < CIN; kq += 4) {
        const float* bp = sW1t + kq * W1S + lane * 4;
        float4 b0 = *(const float4*)(bp);
        float4 b1v = *(const float4*)(bp + W1S);
        float4 b2v = *(const float4*)(bp + 2 * W1S);
        float4 b3v = *(const float4*)(bp + 3 * W1S);
#pragma unroll
        for (int i = 0; i < 8; ++i) {
            float4 a = *(const float4*)(aBase + i * CIN + kq);
            acc[i].x = fmaf(a.x, b0.x, acc[i].x);
            acc[i].y = fmaf(a.x, b0.y, acc[i].y);
            acc[i].z = fmaf(a.x, b0.z, acc[i].z);
            acc[i].w = fmaf(a.x, b0.w, acc[i].w);
            acc[i].x = fmaf(a.y, b1v.x, acc[i].x);
            acc[i].y = fmaf(a.y, b1v.y, acc[i].y);
            acc[i].z = fmaf(a.y, b1v.z, acc[i].z);
            acc[i].w = fmaf(a.y, b1v.w, acc[i].w);
            acc[i].x = fmaf(a.z, b2v.x, acc[i].x);
            acc[i].y = fmaf(a.z, b2v.y, acc[i].y);
            acc[i].z = fmaf(a.z, b2v.z, acc[i].z);
            acc[i].w = fmaf(a.z, b2v.w, acc[i].w);
            acc[i].x = fmaf(a.w, b3v.x, acc[i].x);
            acc[i].y = fmaf(a.w, b3v.y, acc[i].y);
            acc[i].z = fmaf(a.w, b3v.z, acc[i].z);
            acc[i].w = fmaf(a.w, b3v.w, acc[i].w);
        }
    }
    __syncthreads();   // done reading sX and sW1t

    // ---- epilogue1: h = relu(c1*acc + b1) -> sX ; restage W2t into alias
    {
        float4 bb = *(const float4*)(sB1 + lane * 4);
#pragma unroll
        for (int i = 0; i < 8; ++i) {
            int r = warp * 8 + i;
            float c1 = sC1[r];
            float4 h;
            h.x = fmaxf(fmaf(c1, acc[i].x, bb.x), 0.f);
            h.y = fmaxf(fmaf(c1, acc[i].y, bb.y), 0.f);
            h.z = fmaxf(fmaf(c1, acc[i].z, bb.z), 0.f);
            h.w = fmaxf(fmaf(c1, acc[i].w, bb.w), 0.f);
            *(float4*)(sX + r * CIN + lane * 4) = h;
        }
    }
    // stage W2 transposed: sW2t[k*W2S + c] = W2[c*CHID + k]  (L2-resident)
    for (int idx = tid; idx < COUT * CHID; idx += NTHREADS) {
        int c = idx >> 7;
        int k = idx & 127;
        sW2t[k * W2S + c] = W2[idx];
    }
    __syncthreads();

    // ---- GEMM2: o[64][64] = h @ W2^T ; thread tile 8 rows x 2 cols
    float2 acc2[8];
#pragma unroll
    for (int i = 0; i < 8; ++i) acc2[i] = make_float2(0.f, 0.f);

#pragma unroll 2
    for (int kq = 0; kq < CHID; kq += 4) {
        const float* cp = sW2t + kq * W2S + lane * 2;
        float2 c0 = *(const float2*)(cp);
        float2 c1v = *(const float2*)(cp + W2S);
        float2 c2v = *(const float2*)(cp + 2 * W2S);
        float2 c3v = *(const float2*)(cp + 3 * W2S);
#pragma unroll
        for (int i = 0; i < 8; ++i) {
            float4 a = *(const float4*)(aBase + i * CIN + kq);
            acc2[i].x = fmaf(a.x, c0.x, acc2[i].x);
            acc2[i].y = fmaf(a.x, c0.y, acc2[i].y);
            acc2[i].x = fmaf(a.y, c1v.x, acc2[i].x);
            acc2[i].y = fmaf(a.y, c1v.y, acc2[i].y);
            acc2[i].x = fmaf(a.z, c2v.x, acc2[i].x);
            acc2[i].y = fmaf(a.z, c2v.y, acc2[i].y);
            acc2[i].x = fmaf(a.w, c3v.x, acc2[i].x);
            acc2[i].y = fmaf(a.w, c3v.y, acc2[i].y);
        }
    }

    // write o = c2*acc2 + b2 into sO (disjoint from sW2t region)
#pragma unroll
    for (int i = 0; i < 8; ++i) {
        int r = warp * 8 + i;
        float c2v = sC2[r];
        sO[r * COUT + lane * 2 + 0] = fmaf(c2v, acc2[i].x, sB2[lane * 2 + 0]);
        sO[r * COUT + lane * 2 + 1] = fmaf(c2v, acc2[i].y, sB2[lane * 2 + 1]);
    }
    __syncwarp();   // each warp reads back only its own 8 rows

    // ---- log_softmax per row; warp handles its 8 rows, 2 cols per lane
#pragma unroll
    for (int j = 0; j < 8; ++j) {
        int r = warp * 8 + j;
        int grow = row0 + r;
        if (grow >= N_NODES) continue;   // uniform across warp
        float v0 = sO[r * COUT + lane];
        float v1 = sO[r * COUT + lane + 32];
        float m = fmaxf(v0, v1);
#pragma unroll
        for (int off = 16; off; off >>= 1)
            m = fmaxf(m, __shfl_xor_sync(0xffffffffu, m, off));
        float s = expf(v0 - m) + expf(v1 - m);
#pragma unroll
        for (int off = 16; off; off >>= 1)
            s += __shfl_xor_sync(0xffffffffu, s, off);
        float lse = m + logf(s);
        out[(size_t)grow * COUT + lane]      = v0 - lse;
        out[(size_t)grow * COUT + lane + 32] = v1 - lse;
    }
}

extern "C" void kernel_launch(void* const* d_in, const int* in_sizes, int n_in,
                              void* d_out, int out_size)
{
    const float* x    = (const float*)d_in[0];
    // d_in[1] = neighbors (unused)
    const int*   mask = (const int*)d_in[2];
    const float* W1   = (const float*)d_in[3];
    const float* b1   = (const float*)d_in[4];
    const float* W2   = (const float*)d_in[5];
    const float* b2   = (const float*)d_in[6];
    float*       out  = (float*)d_out;

    cudaFuncSetAttribute(fused_gcn_kernel,
                         cudaFuncAttributeMaxDynamicSharedMemorySize, SMEM_BYTES);

    const int grid = (N_NODES + TM - 1) / TM;   // 782
    fused_gcn_kernel<<<grid, NTHREADS, SMEM_BYTES>>>(x, mask, W1, b1, W2, b2, out);
}